// round 13
// baseline (speedup 1.0000x reference)
#include <cuda_runtime.h>
#include <cuda_fp16.h>
#include <math.h>

// ContractiveMessageBlock — Round 12 (= R11 resubmit after infra failure):
// 2 CTAs/SM (smem 108.5 KB), 256 threads, TM=128, single-pass fp16 HMMA,
// silu-from-fragments, 8-edge two-pass dump/epilogue (SCR 32 KB), single W
// slot with cp.async overlap, split0 in global, Wr from L2, rbf broadcast-LDS.

#define E_TOT   200000
#define FEAT    128
#define TM      128
#define THREADS 256
#define NBLK    ((E_TOT + TM - 1) / TM)   // 1563
#define NB      2000
#define NRBF    20
#define PI_OVER_CUT 0.62831853071795864769f

typedef unsigned long long u64;
typedef unsigned int u32;

// ---------------- f32x2 / misc helpers ----------------
__device__ __forceinline__ u64 fma2(u64 a, u64 b, u64 c) {
    u64 d; asm("fma.rn.f32x2 %0, %1, %2, %3;" : "=l"(d) : "l"(a), "l"(b), "l"(c)); return d;
}
__device__ __forceinline__ u64 mul2(u64 a, u64 b) {
    u64 d; asm("mul.rn.f32x2 %0, %1, %2;" : "=l"(d) : "l"(a), "l"(b)); return d;
}
__device__ __forceinline__ u64 add2(u64 a, u64 b) {
    u64 d; asm("add.rn.f32x2 %0, %1, %2;" : "=l"(d) : "l"(a), "l"(b)); return d;
}
__device__ __forceinline__ u64 dup2(float x) {
    u64 d; asm("mov.b64 %0, {%1, %1};" : "=l"(d) : "f"(x)); return d;
}
__device__ __forceinline__ u64 pk2(float a, float b) {
    u64 d; asm("mov.b64 %0, {%1, %2};" : "=l"(d) : "f"(a), "f"(b)); return d;
}
__device__ __forceinline__ void unpack2(u64 a, float& lo, float& hi) {
    asm("mov.b64 {%0, %1}, %2;" : "=f"(lo), "=f"(hi) : "l"(a));
}
__device__ __forceinline__ void red_add_v4(float* p, float a, float b, float c, float d) {
    asm volatile("red.global.add.v4.f32 [%0], {%1, %2, %3, %4};"
                 :: "l"(p), "f"(a), "f"(b), "f"(c), "f"(d) : "memory");
}
__device__ __forceinline__ u32 smem_u32(const void* p) {
    u32 a; asm("{ .reg .u64 t; cvta.to.shared.u64 t, %1; cvt.u32.u64 %0, t; }"
               : "=r"(a) : "l"(p));
    return a;
}
__device__ __forceinline__ void cpa16(u32 s, const void* g) {
    asm volatile("cp.async.cg.shared.global [%0], [%1], 16;" :: "r"(s), "l"(g));
}
__device__ __forceinline__ void cpa_commit() {
    asm volatile("cp.async.commit_group;" ::: "memory");
}
__device__ __forceinline__ void cpa_wait0() {
    asm volatile("cp.async.wait_group 0;" ::: "memory");
}

// ---------------- mma / ldmatrix ----------------
__device__ __forceinline__ void ldsm4(u32* r, u32 addr) {
    asm volatile("ldmatrix.sync.aligned.m8n8.x4.shared.b16 {%0,%1,%2,%3}, [%4];"
                 : "=r"(r[0]), "=r"(r[1]), "=r"(r[2]), "=r"(r[3]) : "r"(addr));
}
__device__ __forceinline__ void mma16816(float* d, const u32* a, u32 b0, u32 b1) {
    asm volatile(
        "mma.sync.aligned.m16n8k16.row.col.f32.f16.f16.f32 "
        "{%0,%1,%2,%3}, {%4,%5,%6,%7}, {%8,%9}, {%0,%1,%2,%3};"
        : "+f"(d[0]), "+f"(d[1]), "+f"(d[2]), "+f"(d[3])
        : "r"(a[0]), "r"(a[1]), "r"(a[2]), "r"(a[3]), "r"(b0), "r"(b1));
}

// fp16 tile [128 rows][128 k]: 16B granules, XOR swizzle.
__device__ __host__ __forceinline__ int toff(int row, int kg) {
    return row * 256 + (((kg ^ (row & 7)) & 15) << 4);
}
// fp32 scratch [64 rows][128 c], 4-word-granule XOR swizzle.
__device__ __forceinline__ int scr_w(int e, int c) {
    return e * 128 + (((((c >> 2)) ^ (e & 7)) & 31) << 2) + (c & 3);
}
__device__ __forceinline__ float silu_f(float x) {
    return x / (1.0f + __expf(-x));
}

// ---------------- global scratch ----------------
__device__ __align__(16) float g_acc_s[NB * FEAT];      // [bin][f]
__device__ __align__(16) float g_acc_v[NB * 3 * FEAT];  // [bin][x][f]
__device__ float g_cnt[NB];
__device__ __align__(16) float g_split0[(size_t)NBLK * TM * FEAT];  // chunk-0 stash
__device__ __align__(16) unsigned char g_W1[32768];          // fp16 tile
__device__ __align__(16) unsigned char g_W2[3 * 32768];      // fp16 tiles

// ---------------- smem offsets (bytes) ----------------
#define OFF_A    0        // 32768  A then H, fp16 [128][128]
#define OFF_W    32768    // 32768  current W tile (fp16)
#define OFF_SCR  65536    // 32768  fp32 D dump [64 rows][128] (warp w rows w*8..w*8+7)
#define OFF_RBF  98304    // 10240  rbf [20][128]
#define OFF_UNIT 108544   // 1536   [3][128]
#define OFF_ENV  110080   // 512
#define OFF_BIN  110592   // 512 (int)
#define SMEM_BYTES 111104

__global__ void cmb_zero() {
    int i = blockIdx.x * 256 + threadIdx.x;
    if (i < NB * FEAT)     g_acc_s[i] = 0.0f;
    if (i < NB * 3 * FEAT) g_acc_v[i] = 0.0f;
    if (i < NB)            g_cnt[i]   = 0.0f;
}

// W1/W2 -> fp16 tiles in swizzled [n][k] layout (B operand, TN gemm).
__global__ void cmb_prep(const float* __restrict__ W1, const float* __restrict__ W2) {
    int i = blockIdx.x * 256 + threadIdx.x;     // 0..65535
    if (i < 16384) {
        int n = i & 127, k = i >> 7;
        float v = W1[k * 128 + n];
        int off = toff(n, k >> 3) + (k & 7) * 2;
        *(__half*)(g_W1 + off) = __float2half_rn(v);
    } else if (i < 65536) {
        int r = i - 16384;
        int c = r >> 14;
        int t = r & 16383;
        int n = t & 127, k = t >> 7;
        float v = W2[k * 384 + c * 128 + n];
        int off = c * 32768 + toff(n, k >> 3) + (k & 7) * 2;
        *(__half*)(g_W2 + off) = __float2half_rn(v);
    }
}

// Issue cp.async for one 32KB W tile.
__device__ __forceinline__ void copyW_async(u32 dst, const unsigned char* g, int tid) {
    #pragma unroll
    for (int t = 0; t < 8; t++) {
        int i = tid + t * THREADS;
        cpa16(dst + i * 16, g + i * 16);
    }
    cpa_commit();
}

// Single-pass fp16 GEMM: acc += A(warp stripe) * B. 128 HMMA per call.
__device__ __forceinline__ void gemm_tile(u32 aT, u32 bW,
                                          int m0, int lane, float acc[16][4]) {
    const int r  = lane & 7;
    const int hf = (lane >> 3) & 1;
    const int kq = lane >> 4;
    const int arow = m0 + hf * 8 + r;
    const int brow = hf * 8 + r;
    #pragma unroll
    for (int ks = 0; ks < 8; ks++) {
        int kg = ks * 2 + kq;
        u32 a[4];
        ldsm4(a, aT + (u32)toff(arow, kg));
        #pragma unroll
        for (int ng = 0; ng < 8; ng++) {
            u32 b[4];
            ldsm4(b, bW + (u32)toff(ng * 16 + brow, kg));
            mma16816(acc[2 * ng],     a, b[0], b[2]);
            mma16816(acc[2 * ng + 1], a, b[1], b[3]);
        }
    }
}

// Dump one 8-row pass (p=0: fragment rows r0; p=1: rows r0+8) into warp's stripe.
__device__ __forceinline__ void dump_pass(float* scr, const float acc[16][4],
                                          int warp, int lane, int p) {
    const int row = warp * 8 + (lane >> 2);
    const int cb  = (lane & 3) * 2;
    #pragma unroll
    for (int ng = 0; ng < 8; ng++)
        #pragma unroll
        for (int s = 0; s < 2; s++) {
            int c = ng * 16 + s * 8 + cb;
            const float* a = acc[2 * ng + s];
            *(float2*)&scr[scr_w(row, c)] = make_float2(a[2 * p], a[2 * p + 1]);
        }
}

// Fused epilogue for chunk C, one 8-edge pass. Wr streamed from global (L2).
template <int C>
__device__ __forceinline__ void epi_pass(
    const float* sScr, const float* sRbfT, const float* sUnit,
    const float* sEnv, const int* sBin,
    const float* __restrict__ v_i, const float* __restrict__ Wr_g,
    const float* __restrict__ b2, const float* __restrict__ br,
    long e0, int nvalid, int warp, int lane, int p)
{
    const int j0  = lane * 4;
    const int ebl = warp * 16 + p * 8;
    const int sr  = warp * 8;

    float4 brv = *(const float4*)&br[C * 128 + j0];
    u64 ws0[8], ws1[8];
    #pragma unroll
    for (int e = 0; e < 8; e++) {
        ws0[e] = pk2(brv.x, brv.y);
        ws1[e] = pk2(brv.z, brv.w);
    }
    #pragma unroll
    for (int n = 0; n < NRBF; n++) {
        float4 w = *(const float4*)&Wr_g[n * 384 + C * 128 + j0];
        u64 wa = pk2(w.x, w.y), wb = pk2(w.z, w.w);
        #pragma unroll
        for (int e = 0; e < 8; e++) {
            u64 f = dup2(sRbfT[n * 128 + ebl + e]);   // broadcast LDS
            ws0[e] = fma2(f, wa, ws0[e]);
            ws1[e] = fma2(f, wb, ws1[e]);
        }
    }

    float4 b2v = *(const float4*)&b2[C * 128 + j0];
    u64 b2a = pk2(b2v.x, b2v.y), b2b = pk2(b2v.z, b2v.w);

    #pragma unroll
    for (int e = 0; e < 8; e++) {
        int ei = ebl + e;
        float4 d = *(const float4*)&sScr[scr_w(sr + e, j0)];
        u64 envd = dup2(sEnv[ei]);
        u64 i01 = mul2(add2(pk2(d.x, d.y), b2a), mul2(ws0[e], envd));
        u64 i23 = mul2(add2(pk2(d.z, d.w), b2b), mul2(ws1[e], envd));
        float i0, i1, i2, i3;
        unpack2(i01, i0, i1); unpack2(i23, i2, i3);

        if (ei < nvalid) {
            if (C == 0) {
                *(float4*)&g_split0[((size_t)e0 + ei) * FEAT + j0] =
                    make_float4(i0, i1, i2, i3);
            } else if (C == 1) {
                int bin = sBin[ei];
                red_add_v4(&g_acc_s[bin * FEAT + j0], i0, i1, i2, i3);
            } else {
                int bin = sBin[ei];
                float4 s0 = *(const float4*)&g_split0[((size_t)e0 + ei) * FEAT + j0];
                const float4* vg =
                    (const float4*)(v_i + (((size_t)e0 + ei) * FEAT + j0) * 3);
                float4 va = vg[0], vb = vg[1], vc2 = vg[2];
                float vf[12] = { va.x, va.y, va.z, va.w,
                                 vb.x, vb.y, vb.z, vb.w,
                                 vc2.x, vc2.y, vc2.z, vc2.w };
                float uu[3] = { sUnit[ei], sUnit[128 + ei], sUnit[256 + ei] };
                #pragma unroll
                for (int x = 0; x < 3; x++)
                    red_add_v4(&g_acc_v[bin * 3 * FEAT + x * FEAT + j0],
                        fmaf(i0, uu[x], s0.x * vf[0 + x]),
                        fmaf(i1, uu[x], s0.y * vf[3 + x]),
                        fmaf(i2, uu[x], s0.z * vf[6 + x]),
                        fmaf(i3, uu[x], s0.w * vf[9 + x]));
            }
        }
    }
}

__global__ void __launch_bounds__(THREADS, 2)
cmb_main(const float* __restrict__ s_i, const float* __restrict__ v_i,
         const float* __restrict__ r_iI, const float* __restrict__ b1,
         const float* __restrict__ b2, const float* __restrict__ Wr_g,
         const float* __restrict__ br, const int* __restrict__ mapping)
{
    extern __shared__ char smem[];
    const u32 sb = smem_u32(smem);
    float* sScr  = (float*)(smem + OFF_SCR);
    float* sRbfT = (float*)(smem + OFF_RBF);
    float* sUnit = (float*)(smem + OFF_UNIT);
    float* sEnv  = (float*)(smem + OFF_ENV);
    int*   sBin  = (int*)(smem + OFF_BIN);

    const int tid  = threadIdx.x;
    const int lane = tid & 31;
    const int warp = tid >> 5;
    const int m0   = warp * 16;
    const long e0  = (long)blockIdx.x * TM;
    const int nvalid = (int)min((long)TM, (long)E_TOT - e0);

    // ---- prefetch W1 ----
    copyW_async(sb + OFF_W, g_W1, tid);

    // ---- A tile: s_i -> fp16 swizzled ----
    for (int i = tid; i < 2048; i += THREADS) {
        int row = i >> 4, kg = i & 15;
        float4 va, vb;
        if (row < nvalid) {
            const float4* g = (const float4*)(s_i + ((size_t)(e0 + row)) * FEAT + kg * 8);
            va = g[0]; vb = g[1];
        } else {
            va = make_float4(0.f, 0.f, 0.f, 0.f); vb = va;
        }
        __half2 h0 = __floats2half2_rn(va.x, va.y);
        __half2 h1 = __floats2half2_rn(va.z, va.w);
        __half2 h2 = __floats2half2_rn(vb.x, vb.y);
        __half2 h3 = __floats2half2_rn(vb.z, vb.w);
        int off = toff(row, kg);
        *(uint4*)(smem + OFF_A + off) =
            make_uint4(*(u32*)&h0, *(u32*)&h1, *(u32*)&h2, *(u32*)&h3);
    }
    // ---- per-edge preprocess (sin recurrence fills rbf array) ----
    if (tid < TM) {
        int e = tid;
        if (e < nvalid) {
            long eg = e0 + e;
            float r0 = r_iI[eg * 3 + 0], r1 = r_iI[eg * 3 + 1], r2 = r_iI[eg * 3 + 2];
            float d = sqrtf(r0 * r0 + r1 * r1 + r2 * r2 + 3e-8f);
            float id = 1.0f / d;
            sUnit[0 * 128 + e] = r0 * id;
            sUnit[1 * 128 + e] = r1 * id;
            sUnit[2 * 128 + e] = r2 * id;
            float theta = PI_OVER_CUT * d;
            float s1, c1;
            sincosf(theta, &s1, &c1);
            sEnv[e] = (d < 5.0f) ? 0.5f * (c1 + 1.0f) : 0.0f;
            float twoc = 2.0f * c1;
            float sp = 0.0f, sn = s1;
            #pragma unroll
            for (int n = 0; n < NRBF; n++) {
                sRbfT[n * 128 + e] = sn * id;
                float nx = twoc * sn - sp;
                sp = sn; sn = nx;
            }
            int b = mapping[eg];
            sBin[e] = b;
            atomicAdd(&g_cnt[b], 1.0f);
        } else {
            sUnit[e] = sUnit[128 + e] = sUnit[256 + e] = 0.0f;
            sEnv[e] = 0.0f; sBin[e] = 0;
            #pragma unroll
            for (int n = 0; n < NRBF; n++) sRbfT[n * 128 + e] = 0.0f;
        }
    }
    cpa_wait0();
    __syncthreads();          // A, W1, preprocess visible

    float acc[16][4];

    // ---- GEMM1 ----
    #pragma unroll
    for (int q = 0; q < 16; q++)
        acc[q][0] = acc[q][1] = acc[q][2] = acc[q][3] = 0.0f;
    gemm_tile(sb + OFF_A, sb + OFF_W, m0, lane, acc);
    __syncthreads();          // all warps done reading W1
    copyW_async(sb + OFF_W, g_W2, tid);          // prefetch chunk0

    // ---- silu directly from fragments -> H fp16 (warp-local rows) ----
    {
        const int r0 = m0 + (lane >> 2);
        const int cb = (lane & 3) * 2;
        #pragma unroll
        for (int ng = 0; ng < 8; ng++)
            #pragma unroll
            for (int s = 0; s < 2; s++) {
                int c = ng * 16 + s * 8 + cb;
                float2 bb = *(const float2*)&b1[c];
                const float* a = acc[2 * ng + s];
                __half2 hA = __floats2half2_rn(silu_f(a[0] + bb.x),
                                               silu_f(a[1] + bb.y));
                __half2 hB = __floats2half2_rn(silu_f(a[2] + bb.x),
                                               silu_f(a[3] + bb.y));
                int kg = c >> 3, kb = (c & 7) * 2;
                *(__half2*)(smem + OFF_A + toff(r0,     kg) + kb) = hA;
                *(__half2*)(smem + OFF_A + toff(r0 + 8, kg) + kb) = hB;
            }
    }
    cpa_wait0();
    __syncthreads();          // H + W2[0] ready

    // ---- 3 GEMM2 chunks ----
    #pragma unroll
    for (int c = 0; c < 3; c++) {
        #pragma unroll
        for (int q = 0; q < 16; q++)
            acc[q][0] = acc[q][1] = acc[q][2] = acc[q][3] = 0.0f;
        gemm_tile(sb + OFF_A, sb + OFF_W, m0, lane, acc);
        __syncthreads();      // all warps done reading W[c]
        if (c < 2)
            copyW_async(sb + OFF_W, g_W2 + (c + 1) * 32768, tid);

        dump_pass(sScr, acc, warp, lane, 0);
        __syncwarp();
        if (c == 0)
            epi_pass<0>(sScr, sRbfT, sUnit, sEnv, sBin, v_i, Wr_g, b2, br,
                        e0, nvalid, warp, lane, 0);
        else if (c == 1)
            epi_pass<1>(sScr, sRbfT, sUnit, sEnv, sBin, v_i, Wr_g, b2, br,
                        e0, nvalid, warp, lane, 0);
        else
            epi_pass<2>(sScr, sRbfT, sUnit, sEnv, sBin, v_i, Wr_g, b2, br,
                        e0, nvalid, warp, lane, 0);
        __syncwarp();
        dump_pass(sScr, acc, warp, lane, 1);
        __syncwarp();
        if (c == 0)
            epi_pass<0>(sScr, sRbfT, sUnit, sEnv, sBin, v_i, Wr_g, b2, br,
                        e0, nvalid, warp, lane, 1);
        else if (c == 1)
            epi_pass<1>(sScr, sRbfT, sUnit, sEnv, sBin, v_i, Wr_g, b2, br,
                        e0, nvalid, warp, lane, 1);
        else
            epi_pass<2>(sScr, sRbfT, sUnit, sEnv, sBin, v_i, Wr_g, b2, br,
                        e0, nvalid, warp, lane, 1);

        if (c < 2) {
            cpa_wait0();
            __syncthreads();  // next W arrived; SCR reuse is warp-local
        }
    }
}

__global__ void cmb_final(float* __restrict__ out) {
    int bin = blockIdx.x;
    int f   = threadIdx.x;
    float ic = 1.0f / fmaxf(g_cnt[bin], 1.0f);
    out[bin * FEAT + f] = g_acc_s[bin * FEAT + f] * ic;
    #pragma unroll
    for (int x = 0; x < 3; x++)
        out[NB * FEAT + bin * 384 + f * 3 + x] =
            g_acc_v[bin * 3 * FEAT + x * FEAT + f] * ic;
}

extern "C" void kernel_launch(void* const* d_in, const int* in_sizes, int n_in,
                              void* d_out, int out_size)
{
    const float* s_i     = (const float*)d_in[0];
    const float* v_i     = (const float*)d_in[1];
    const float* r_iI    = (const float*)d_in[2];
    const float* W1      = (const float*)d_in[3];
    const float* b1      = (const float*)d_in[4];
    const float* W2      = (const float*)d_in[5];
    const float* b2      = (const float*)d_in[6];
    const float* Wr      = (const float*)d_in[7];
    const float* br      = (const float*)d_in[8];
    const int*   mapping = (const int*)d_in[9];
    float* out = (float*)d_out;
    (void)in_sizes; (void)n_in; (void)out_size;

    cudaFuncSetAttribute((const void*)cmb_main,
                         cudaFuncAttributeMaxDynamicSharedMemorySize, SMEM_BYTES);

    cmb_prep<<<256, 256>>>(W1, W2);
    cmb_zero<<<(NB * 3 * FEAT + 255) / 256, 256>>>();
    cmb_main<<<NBLK, THREADS, SMEM_BYTES>>>(s_i, v_i, r_iI, b1, b2, Wr, br, mapping);
    cmb_final<<<NB, FEAT>>>(out);
}

// round 14
// speedup vs baseline: 1.7116x; 1.7116x over previous
#include <cuda_runtime.h>
#include <cuda_fp16.h>
#include <math.h>

// ContractiveMessageBlock — Round 13: barrier-free warp-autonomous kernel.
// All 4 W tiles resident in smem (one __syncthreads at start, none after).
// Each warp work-steals 16-edge slices via a global counter and runs the full
// pipeline on private smem regions (A 4KB, SCR 4KB, rbf/unit/env/bin).

#define E_TOT   200000
#define FEAT    128
#define SLICE   16
#define NSLICES (E_TOT / SLICE)   // 12500 exactly
#define THREADS 256
#define NCTAS   152
#define NB      2000
#define NRBF    20
#define PI_OVER_CUT 0.62831853071795864769f

typedef unsigned long long u64;
typedef unsigned int u32;

// ---------------- f32x2 / misc helpers ----------------
__device__ __forceinline__ u64 fma2(u64 a, u64 b, u64 c) {
    u64 d; asm("fma.rn.f32x2 %0, %1, %2, %3;" : "=l"(d) : "l"(a), "l"(b), "l"(c)); return d;
}
__device__ __forceinline__ u64 mul2(u64 a, u64 b) {
    u64 d; asm("mul.rn.f32x2 %0, %1, %2;" : "=l"(d) : "l"(a), "l"(b)); return d;
}
__device__ __forceinline__ u64 add2(u64 a, u64 b) {
    u64 d; asm("add.rn.f32x2 %0, %1, %2;" : "=l"(d) : "l"(a), "l"(b)); return d;
}
__device__ __forceinline__ u64 dup2(float x) {
    u64 d; asm("mov.b64 %0, {%1, %1};" : "=l"(d) : "f"(x)); return d;
}
__device__ __forceinline__ u64 pk2(float a, float b) {
    u64 d; asm("mov.b64 %0, {%1, %2};" : "=l"(d) : "f"(a), "f"(b)); return d;
}
__device__ __forceinline__ void unpack2(u64 a, float& lo, float& hi) {
    asm("mov.b64 {%0, %1}, %2;" : "=f"(lo), "=f"(hi) : "l"(a));
}
__device__ __forceinline__ void red_add_v4(float* p, float a, float b, float c, float d) {
    asm volatile("red.global.add.v4.f32 [%0], {%1, %2, %3, %4};"
                 :: "l"(p), "f"(a), "f"(b), "f"(c), "f"(d) : "memory");
}
__device__ __forceinline__ u32 smem_u32(const void* p) {
    u32 a; asm("{ .reg .u64 t; cvta.to.shared.u64 t, %1; cvt.u32.u64 %0, t; }"
               : "=r"(a) : "l"(p));
    return a;
}
__device__ __forceinline__ void cpa16(u32 s, const void* g) {
    asm volatile("cp.async.cg.shared.global [%0], [%1], 16;" :: "r"(s), "l"(g));
}
__device__ __forceinline__ void cpa_commit() {
    asm volatile("cp.async.commit_group;" ::: "memory");
}
__device__ __forceinline__ void cpa_wait0() {
    asm volatile("cp.async.wait_group 0;" ::: "memory");
}

// ---------------- mma / ldmatrix ----------------
__device__ __forceinline__ void ldsm4(u32* r, u32 addr) {
    asm volatile("ldmatrix.sync.aligned.m8n8.x4.shared.b16 {%0,%1,%2,%3}, [%4];"
                 : "=r"(r[0]), "=r"(r[1]), "=r"(r[2]), "=r"(r[3]) : "r"(addr));
}
__device__ __forceinline__ void mma16816(float* d, const u32* a, u32 b0, u32 b1) {
    asm volatile(
        "mma.sync.aligned.m16n8k16.row.col.f32.f16.f16.f32 "
        "{%0,%1,%2,%3}, {%4,%5,%6,%7}, {%8,%9}, {%0,%1,%2,%3};"
        : "+f"(d[0]), "+f"(d[1]), "+f"(d[2]), "+f"(d[3])
        : "r"(a[0]), "r"(a[1]), "r"(a[2]), "r"(a[3]), "r"(b0), "r"(b1));
}

// fp16 tile [rows][128 k]: 16B granules, XOR swizzle (local rows 0..15 or 0..127).
__device__ __host__ __forceinline__ int toff(int row, int kg) {
    return row * 256 + (((kg ^ (row & 7)) & 15) << 4);
}
// fp32 scratch [8 rows][128 c] per warp, 4-word-granule XOR swizzle.
__device__ __forceinline__ int scr_w(int e, int c) {
    return e * 128 + (((((c >> 2)) ^ (e & 7)) & 31) << 2) + (c & 3);
}
__device__ __forceinline__ float silu_f(float x) {
    return x / (1.0f + __expf(-x));
}

// ---------------- global scratch ----------------
__device__ __align__(16) float g_acc_s[NB * FEAT];      // [bin][f]
__device__ __align__(16) float g_acc_v[NB * 3 * FEAT];  // [bin][x][f]
__device__ float g_cnt[NB];
__device__ u32 g_slice;
__device__ __align__(16) unsigned char g_W1[32768];          // fp16 tile
__device__ __align__(16) unsigned char g_W2[3 * 32768];      // fp16 tiles

// ---------------- smem offsets (bytes) ----------------
#define OFF_W    0                      // 131072: W1, c0, c1, c2 (resident)
#define OFF_A    131072                 // 8 * 4096 per-warp A/H fp16 [16][128]
#define OFF_SCR  163840                 // 8 * 4096 per-warp fp32 [8][128]
#define OFF_RBF  196608                 // 8 * 1280 per-warp [20][16]
#define OFF_UNIT 206848                 // 8 * 192  per-warp [3][16]
#define OFF_ENV  208384                 // 8 * 64
#define OFF_BIN  208896                 // 8 * 64 (int)
#define SMEM_BYTES 209408

__global__ void cmb_zero() {
    int i = blockIdx.x * 256 + threadIdx.x;
    if (i < NB * FEAT)     g_acc_s[i] = 0.0f;
    if (i < NB * 3 * FEAT) g_acc_v[i] = 0.0f;
    if (i < NB)            g_cnt[i]   = 0.0f;
    if (i == 0)            g_slice    = 0;
}

// W1/W2 -> fp16 tiles in swizzled [n][k] layout (B operand, TN gemm).
__global__ void cmb_prep(const float* __restrict__ W1, const float* __restrict__ W2) {
    int i = blockIdx.x * 256 + threadIdx.x;     // 0..65535
    if (i < 16384) {
        int n = i & 127, k = i >> 7;
        float v = W1[k * 128 + n];
        int off = toff(n, k >> 3) + (k & 7) * 2;
        *(__half*)(g_W1 + off) = __float2half_rn(v);
    } else if (i < 65536) {
        int r = i - 16384;
        int c = r >> 14;
        int t = r & 16383;
        int n = t & 127, k = t >> 7;
        float v = W2[k * 384 + c * 128 + n];
        int off = c * 32768 + toff(n, k >> 3) + (k & 7) * 2;
        *(__half*)(g_W2 + off) = __float2half_rn(v);
    }
}

// GEMM over one warp slice: acc[16][4] += A[16x128] * B[128x128]. 128 HMMA.
__device__ __forceinline__ void gemm_tile(u32 aT, u32 bW, int lane, float acc[16][4]) {
    const int r  = lane & 7;
    const int hf = (lane >> 3) & 1;
    const int kq = lane >> 4;
    const int arow = hf * 8 + r;
    #pragma unroll
    for (int ks = 0; ks < 8; ks++) {
        int kg = ks * 2 + kq;
        u32 a[4];
        ldsm4(a, aT + (u32)toff(arow, kg));
        #pragma unroll
        for (int ng = 0; ng < 8; ng++) {
            u32 b[4];
            ldsm4(b, bW + (u32)toff(ng * 16 + arow, kg));
            mma16816(acc[2 * ng],     a, b[0], b[2]);
            mma16816(acc[2 * ng + 1], a, b[1], b[3]);
        }
    }
}

// Dump pass p (edges p*8..p*8+7) into warp's 8-row SCR stripe.
__device__ __forceinline__ void dump_pass(float* scr, const float acc[16][4],
                                          int lane, int p) {
    const int row = lane >> 2;
    const int cb  = (lane & 3) * 2;
    #pragma unroll
    for (int ng = 0; ng < 8; ng++)
        #pragma unroll
        for (int s = 0; s < 2; s++) {
            int c = ng * 16 + s * 8 + cb;
            const float* a = acc[2 * ng + s];
            *(float2*)&scr[scr_w(row, c)] = make_float2(a[2 * p], a[2 * p + 1]);
        }
}

// Epilogue for chunk C, pass P (8 edges). st0: register stash for chunk-0 inv.
template <int C, int P>
__device__ __forceinline__ void epi_pass(
    const float* sScr, const float* sRbf, const float* sUnit,
    const float* sEnv, const int* sBin,
    const float* __restrict__ v_i, const float* __restrict__ Wr_g,
    const float* __restrict__ b2, const float* __restrict__ br,
    long e0, int lane, float st0[8][4])
{
    const int j0 = lane * 4;

    float4 brv = *(const float4*)&br[C * 128 + j0];
    u64 ws0[8], ws1[8];
    #pragma unroll
    for (int e = 0; e < 8; e++) {
        ws0[e] = pk2(brv.x, brv.y);
        ws1[e] = pk2(brv.z, brv.w);
    }
    #pragma unroll
    for (int n = 0; n < NRBF; n++) {
        float4 w = *(const float4*)&Wr_g[n * 384 + C * 128 + j0];
        u64 wa = pk2(w.x, w.y), wb = pk2(w.z, w.w);
        #pragma unroll
        for (int e = 0; e < 8; e++) {
            u64 f = dup2(sRbf[n * 16 + P * 8 + e]);   // LDS broadcast
            ws0[e] = fma2(f, wa, ws0[e]);
            ws1[e] = fma2(f, wb, ws1[e]);
        }
    }

    float4 b2v = *(const float4*)&b2[C * 128 + j0];
    u64 b2a = pk2(b2v.x, b2v.y), b2b = pk2(b2v.z, b2v.w);

    #pragma unroll
    for (int e = 0; e < 8; e++) {
        int ei = P * 8 + e;                 // local edge in slice
        float4 d = *(const float4*)&sScr[scr_w(e, j0)];
        u64 envd = dup2(sEnv[ei]);
        u64 i01 = mul2(add2(pk2(d.x, d.y), b2a), mul2(ws0[e], envd));
        u64 i23 = mul2(add2(pk2(d.z, d.w), b2b), mul2(ws1[e], envd));
        float i0, i1, i2, i3;
        unpack2(i01, i0, i1); unpack2(i23, i2, i3);

        if (C == 0) {
            st0[e][0] = i0; st0[e][1] = i1; st0[e][2] = i2; st0[e][3] = i3;
        } else if (C == 1) {
            int bin = sBin[ei];
            red_add_v4(&g_acc_s[bin * FEAT + j0], i0, i1, i2, i3);
        } else {
            int bin = sBin[ei];
            const float4* vg =
                (const float4*)(v_i + (((size_t)e0 + ei) * FEAT + j0) * 3);
            float4 va = vg[0], vb = vg[1], vc2 = vg[2];
            float vf[12] = { va.x, va.y, va.z, va.w,
                             vb.x, vb.y, vb.z, vb.w,
                             vc2.x, vc2.y, vc2.z, vc2.w };
            float uu[3] = { sUnit[ei], sUnit[16 + ei], sUnit[32 + ei] };
            #pragma unroll
            for (int x = 0; x < 3; x++)
                red_add_v4(&g_acc_v[bin * 3 * FEAT + x * FEAT + j0],
                    fmaf(i0, uu[x], st0[e][0] * vf[0 + x]),
                    fmaf(i1, uu[x], st0[e][1] * vf[3 + x]),
                    fmaf(i2, uu[x], st0[e][2] * vf[6 + x]),
                    fmaf(i3, uu[x], st0[e][3] * vf[9 + x]));
        }
    }
}

__global__ void __launch_bounds__(THREADS, 1)
cmb_main(const float* __restrict__ s_i, const float* __restrict__ v_i,
         const float* __restrict__ r_iI, const float* __restrict__ b1,
         const float* __restrict__ b2, const float* __restrict__ Wr_g,
         const float* __restrict__ br, const int* __restrict__ mapping)
{
    extern __shared__ char smem[];
    const u32 sb = smem_u32(smem);

    const int tid  = threadIdx.x;
    const int lane = tid & 31;
    const int warp = tid >> 5;

    // per-warp private regions
    const u32 aBuf  = sb + OFF_A   + warp * 4096;
    float* sScr  = (float*)(smem + OFF_SCR + warp * 4096);
    float* sRbf  = (float*)(smem + OFF_RBF + warp * 1280);
    float* sUnit = (float*)(smem + OFF_UNIT + warp * 192);
    float* sEnv  = (float*)(smem + OFF_ENV + warp * 64);
    int*   sBin  = (int*)(smem + OFF_BIN + warp * 64);

    // ---- load ALL W tiles once (W1 + 3 W2 chunks = 128 KB) ----
    {
        #pragma unroll
        for (int t = 0; t < 8; t++) {
            int i = tid + t * THREADS;
            cpa16(sb + OFF_W + i * 16, g_W1 + i * 16);
        }
        #pragma unroll
        for (int t = 0; t < 24; t++) {
            int i = tid + t * THREADS;
            cpa16(sb + OFF_W + 32768 + i * 16, g_W2 + i * 16);
        }
        cpa_commit();
        cpa_wait0();
    }
    __syncthreads();   // the ONLY block barrier

    const u32 bW1 = sb + OFF_W;
    const u32 bC0 = sb + OFF_W + 32768;
    const u32 bC1 = sb + OFF_W + 65536;
    const u32 bC2 = sb + OFF_W + 98304;

    float acc[16][4];
    float st0a[8][4], st0b[8][4];

    // ---- warp-autonomous work-stealing over 16-edge slices ----
    for (;;) {
        u32 s;
        if (lane == 0) s = atomicAdd(&g_slice, 1u);
        s = __shfl_sync(0xFFFFFFFFu, s, 0);
        if (s >= NSLICES) break;
        const long e0 = (long)s * SLICE;

        __syncwarp();   // prior slice's epilogue done before overwriting buffers

        // ---- preprocess (one edge per lane<16) ----
        if (lane < SLICE) {
            long eg = e0 + lane;
            float r0 = r_iI[eg * 3 + 0], r1 = r_iI[eg * 3 + 1], r2 = r_iI[eg * 3 + 2];
            float d = sqrtf(r0 * r0 + r1 * r1 + r2 * r2 + 3e-8f);
            float id = 1.0f / d;
            sUnit[0 * 16 + lane] = r0 * id;
            sUnit[1 * 16 + lane] = r1 * id;
            sUnit[2 * 16 + lane] = r2 * id;
            float theta = PI_OVER_CUT * d;
            float s1, c1;
            sincosf(theta, &s1, &c1);
            sEnv[lane] = (d < 5.0f) ? 0.5f * (c1 + 1.0f) : 0.0f;
            float twoc = 2.0f * c1;
            float sp = 0.0f, sn = s1;
            #pragma unroll
            for (int n = 0; n < NRBF; n++) {
                sRbf[n * 16 + lane] = sn * id;
                float nx = twoc * sn - sp;
                sp = sn; sn = nx;
            }
            int b = mapping[eg];
            sBin[lane] = b;
            atomicAdd(&g_cnt[b], 1.0f);
        }

        // ---- A slice: 16 rows of s_i -> fp16 swizzled (warp-private) ----
        {
            const float4* g = (const float4*)(s_i + (size_t)e0 * FEAT);
            #pragma unroll
            for (int l = 0; l < 8; l++) {
                int i = lane + l * 32;          // 0..255 -> (row, kg)
                int row = i >> 4, kg = i & 15;
                float4 va = g[i * 2], vb = g[i * 2 + 1];
                __half2 h0 = __floats2half2_rn(va.x, va.y);
                __half2 h1 = __floats2half2_rn(va.z, va.w);
                __half2 h2 = __floats2half2_rn(vb.x, vb.y);
                __half2 h3 = __floats2half2_rn(vb.z, vb.w);
                *(uint4*)(smem + (aBuf - sb) + toff(row, kg)) =
                    make_uint4(*(u32*)&h0, *(u32*)&h1, *(u32*)&h2, *(u32*)&h3);
            }
        }
        __syncwarp();

        // ---- GEMM1 ----
        #pragma unroll
        for (int q = 0; q < 16; q++)
            acc[q][0] = acc[q][1] = acc[q][2] = acc[q][3] = 0.0f;
        gemm_tile(aBuf, bW1, lane, acc);

        // ---- silu from fragments -> H fp16 in place (warp-private) ----
        {
            const int r0 = lane >> 2;
            const int cb = (lane & 3) * 2;
            #pragma unroll
            for (int ng = 0; ng < 8; ng++)
                #pragma unroll
                for (int ss = 0; ss < 2; ss++) {
                    int c = ng * 16 + ss * 8 + cb;
                    float2 bb = *(const float2*)&b1[c];
                    const float* a = acc[2 * ng + ss];
                    __half2 hA = __floats2half2_rn(silu_f(a[0] + bb.x),
                                                   silu_f(a[1] + bb.y));
                    __half2 hB = __floats2half2_rn(silu_f(a[2] + bb.x),
                                                   silu_f(a[3] + bb.y));
                    int kg = c >> 3, kb = (c & 7) * 2;
                    *(__half2*)(smem + (aBuf - sb) + toff(r0,     kg) + kb) = hA;
                    *(__half2*)(smem + (aBuf - sb) + toff(r0 + 8, kg) + kb) = hB;
                }
        }
        __syncwarp();

        // ---- chunk 0 ----
        #pragma unroll
        for (int q = 0; q < 16; q++)
            acc[q][0] = acc[q][1] = acc[q][2] = acc[q][3] = 0.0f;
        gemm_tile(aBuf, bC0, lane, acc);
        dump_pass(sScr, acc, lane, 0);
        __syncwarp();
        epi_pass<0, 0>(sScr, sRbf, sUnit, sEnv, sBin, v_i, Wr_g, b2, br, e0, lane, st0a);
        __syncwarp();
        dump_pass(sScr, acc, lane, 1);
        __syncwarp();
        epi_pass<0, 1>(sScr, sRbf, sUnit, sEnv, sBin, v_i, Wr_g, b2, br, e0, lane, st0b);
        __syncwarp();

        // ---- chunk 1 ----
        #pragma unroll
        for (int q = 0; q < 16; q++)
            acc[q][0] = acc[q][1] = acc[q][2] = acc[q][3] = 0.0f;
        gemm_tile(aBuf, bC1, lane, acc);
        dump_pass(sScr, acc, lane, 0);
        __syncwarp();
        epi_pass<1, 0>(sScr, sRbf, sUnit, sEnv, sBin, v_i, Wr_g, b2, br, e0, lane, st0a);
        __syncwarp();
        dump_pass(sScr, acc, lane, 1);
        __syncwarp();
        epi_pass<1, 1>(sScr, sRbf, sUnit, sEnv, sBin, v_i, Wr_g, b2, br, e0, lane, st0b);
        __syncwarp();

        // ---- chunk 2 ----
        #pragma unroll
        for (int q = 0; q < 16; q++)
            acc[q][0] = acc[q][1] = acc[q][2] = acc[q][3] = 0.0f;
        gemm_tile(aBuf, bC2, lane, acc);
        dump_pass(sScr, acc, lane, 0);
        __syncwarp();
        epi_pass<2, 0>(sScr, sRbf, sUnit, sEnv, sBin, v_i, Wr_g, b2, br, e0, lane, st0a);
        __syncwarp();
        dump_pass(sScr, acc, lane, 1);
        __syncwarp();
        epi_pass<2, 1>(sScr, sRbf, sUnit, sEnv, sBin, v_i, Wr_g, b2, br, e0, lane, st0b);
    }
}

__global__ void cmb_final(float* __restrict__ out) {
    int bin = blockIdx.x;
    int f   = threadIdx.x;
    float ic = 1.0f / fmaxf(g_cnt[bin], 1.0f);
    out[bin * FEAT + f] = g_acc_s[bin * FEAT + f] * ic;
    #pragma unroll
    for (int x = 0; x < 3; x++)
        out[NB * FEAT + bin * 384 + f * 3 + x] =
            g_acc_v[bin * 3 * FEAT + x * FEAT + f] * ic;
}

extern "C" void kernel_launch(void* const* d_in, const int* in_sizes, int n_in,
                              void* d_out, int out_size)
{
    const float* s_i     = (const float*)d_in[0];
    const float* v_i     = (const float*)d_in[1];
    const float* r_iI    = (const float*)d_in[2];
    const float* W1      = (const float*)d_in[3];
    const float* b1      = (const float*)d_in[4];
    const float* W2      = (const float*)d_in[5];
    const float* b2      = (const float*)d_in[6];
    const float* Wr      = (const float*)d_in[7];
    const float* br      = (const float*)d_in[8];
    const int*   mapping = (const int*)d_in[9];
    float* out = (float*)d_out;
    (void)in_sizes; (void)n_in; (void)out_size;

    cudaFuncSetAttribute((const void*)cmb_main,
                         cudaFuncAttributeMaxDynamicSharedMemorySize, SMEM_BYTES);

    cmb_prep<<<256, 256>>>(W1, W2);
    cmb_zero<<<(NB * 3 * FEAT + 255) / 256, 256>>>();
    cmb_main<<<NCTAS, THREADS, SMEM_BYTES>>>(s_i, v_i, r_iI, b1, b2, Wr, br, mapping);
    cmb_final<<<NB, FEAT>>>(out);
}